// round 3
// baseline (speedup 1.0000x reference)
#include <cuda_runtime.h>
#include <cstddef>

static constexpr int N_UNITS = 16384;   // units per row (fixed by problem)
static constexpr int K_TOP   = 655;     // winners per row
static constexpr int THREADS = 512;
static constexpr int VPT     = N_UNITS / (THREADS * 4);  // float4 vectors per thread = 8

// Boost factors, computed once per launch (16384 exps total).
__device__ float g_boost[N_UNITS];

__global__ void boost_kernel(const float* __restrict__ duty, int n, float targetDensity) {
    int i = blockIdx.x * blockDim.x + threadIdx.x;
    if (i < n) g_boost[i] = expf(targetDensity - duty[i]);
}

// Order-preserving float -> uint32 map (total order, larger float -> larger key).
__device__ __forceinline__ unsigned mono(float f) {
    unsigned u = __float_as_uint(f);
    return (u & 0x80000000u) ? ~u : (u | 0x80000000u);
}

__global__ __launch_bounds__(THREADS) void kwinners_kernel(
    const float* __restrict__ x, float* __restrict__ out)
{
    extern __shared__ unsigned skeys[];   // N_UNITS keys = 64 KB
    __shared__ unsigned hist[256];
    __shared__ unsigned warpTot[8];
    __shared__ unsigned sh_prefix;
    __shared__ int sh_k;

    const int tid = threadIdx.x;
    const size_t rowOff = (size_t)blockIdx.x * N_UNITS;
    const float4* __restrict__ xr = (const float4*)(x + rowOff);
    const float4* __restrict__ br = (const float4*)g_boost;

    // ---- Load row, apply boost, store monotonic keys to smem ----
    #pragma unroll
    for (int i = 0; i < VPT; i++) {
        int v = tid + THREADS * i;
        float4 xv = __ldg(&xr[v]);
        float4 bv = br[v];
        uint4 kk;
        kk.x = mono(xv.x * bv.x);
        kk.y = mono(xv.y * bv.y);
        kk.z = mono(xv.z * bv.z);
        kk.w = mono(xv.w * bv.w);
        ((uint4*)skeys)[v] = kk;
    }
    if (tid == 0) { sh_prefix = 0u; sh_k = K_TOP; }
    unsigned decided = 0;   // mask of already-decided high bits (identical across threads)

    // ---- 4-level radix select for the K-th largest key ----
    #pragma unroll
    for (int level = 0; level < 4; level++) {
        const int shift = 24 - 8 * level;
        if (tid < 256) hist[tid] = 0u;
        __syncthreads();

        const unsigned prefix = sh_prefix;
        const int k = sh_k;

        // Histogram of the current byte among keys matching the decided prefix.
        #pragma unroll 4
        for (int i = tid; i < N_UNITS; i += THREADS) {
            unsigned kk = skeys[i];
            if ((kk & decided) == prefix)
                atomicAdd(&hist[(kk >> shift) & 0xFFu], 1u);
        }
        __syncthreads();

        // Parallel suffix-sum over 256 bins: warp shfl scans + 8 warp totals.
        unsigned v = 0, s = 0;
        if (tid < 256) {
            v = hist[tid];
            s = v;
            int lane = tid & 31;
            #pragma unroll
            for (int off = 1; off < 32; off <<= 1) {
                unsigned t = __shfl_down_sync(0xFFFFFFFFu, s, off);
                if (lane + off < 32) s += t;
            }
            if (lane == 0) warpTot[tid >> 5] = s;
        }
        __syncthreads();
        if (tid < 256) {
            unsigned above = 0;
            #pragma unroll
            for (int w = 0; w < 8; w++)
                if (w > (tid >> 5)) above += warpTot[w];
            unsigned ssum = s + above;                 // count of keys >= bin 'tid' start
            // unique bin with ssum >= k > ssum - hist[bin]
            if (ssum >= (unsigned)k && (ssum - v) < (unsigned)k) {
                sh_prefix = prefix | ((unsigned)tid << shift);
                sh_k = k - (int)(ssum - v);
            }
        }
        decided |= 0xFFu << shift;
        __syncthreads();
    }

    const unsigned T = sh_prefix;   // exact key of the K-th largest element

    // ---- Write binary mask ----
    float4* __restrict__ orow = (float4*)(out + rowOff);
    #pragma unroll
    for (int i = 0; i < VPT; i++) {
        int v = tid + THREADS * i;
        uint4 kk = ((uint4*)skeys)[v];
        float4 m;
        m.x = (kk.x >= T) ? 1.0f : 0.0f;
        m.y = (kk.y >= T) ? 1.0f : 0.0f;
        m.z = (kk.z >= T) ? 1.0f : 0.0f;
        m.w = (kk.w >= T) ? 1.0f : 0.0f;
        orow[v] = m;
    }
}

extern "C" void kernel_launch(void* const* d_in, const int* in_sizes, int n_in,
                              void* d_out, int out_size) {
    const float* x    = (const float*)d_in[0];   // (B, N) float32
    const float* duty = (const float*)d_in[1];   // (N,)   float32
    float* out        = (float*)d_out;

    const int n = in_sizes[1];                   // 16384
    const int B = in_sizes[0] / n;               // 4096
    const float targetDensity = (float)K_TOP / (float)n;  // 655/16384, exact in fp32

    cudaFuncSetAttribute(kwinners_kernel,
                         cudaFuncAttributeMaxDynamicSharedMemorySize,
                         N_UNITS * (int)sizeof(unsigned));

    boost_kernel<<<(n + 255) / 256, 256>>>(duty, n, targetDensity);
    kwinners_kernel<<<B, THREADS, N_UNITS * sizeof(unsigned)>>>(x, out);
}

// round 7
// speedup vs baseline: 1.0653x; 1.0653x over previous
#include <cuda_runtime.h>
#include <cstddef>

static constexpr int N_UNITS = 16384;
static constexpr int K_TOP   = 655;
static constexpr int THREADS = 512;
static constexpr int VPT4    = N_UNITS / (THREADS * 4);  // float4 vectors per thread = 8
static constexpr int KPT     = VPT4 * 4;                 // keys per thread = 32
static constexpr int NH      = 8;                        // level-0 histogram copies

__device__ float g_boost[N_UNITS];

__global__ void boost_kernel(const float* __restrict__ duty, int n, float targetDensity) {
    int i = blockIdx.x * blockDim.x + threadIdx.x;
    if (i < n) g_boost[i] = expf(targetDensity - duty[i]);
}

// Order-preserving float -> uint32 map (total order, larger float -> larger key).
__device__ __forceinline__ unsigned mono(float f) {
    unsigned u = __float_as_uint(f);
    return (u & 0x80000000u) ? ~u : (u | 0x80000000u);
}

__global__ __launch_bounds__(THREADS, 2) void kwinners_kernel(
    const float* __restrict__ x, float* __restrict__ out)
{
    __shared__ unsigned hist[NH][256];   // 8 KB; level 0 uses all copies, levels 1-3 use hist[0]
    __shared__ unsigned warpTot[8];
    __shared__ unsigned sh_prefix;
    __shared__ int sh_k;

    const int tid = threadIdx.x;
    const size_t rowOff = (size_t)blockIdx.x * N_UNITS;
    const float4* __restrict__ xr = (const float4*)(x + rowOff);
    const float4* __restrict__ br = (const float4*)g_boost;

    // ---- Load row, apply boost; keys stay in registers ----
    unsigned key[KPT];
    #pragma unroll
    for (int i = 0; i < VPT4; i++) {
        int v = tid + THREADS * i;
        float4 xv = __ldcs(&xr[v]);     // read-once: evict-first
        float4 bv = __ldg(&br[v]);      // reused across CTAs: keep cached
        key[4*i + 0] = mono(xv.x * bv.x);
        key[4*i + 1] = mono(xv.y * bv.y);
        key[4*i + 2] = mono(xv.z * bv.z);
        key[4*i + 3] = mono(xv.w * bv.w);
    }
    if (tid == 0) { sh_prefix = 0u; sh_k = K_TOP; }
    unsigned decided = 0;

    // ---- 4-level radix select for the K-th largest key ----
    #pragma unroll 1
    for (int level = 0; level < 4; level++) {
        const int shift = 24 - 8 * level;

        // clear histogram(s)
        if (level == 0) {
            unsigned* hf = &hist[0][0];
            #pragma unroll
            for (int j = 0; j < (NH * 256) / THREADS; j++) hf[tid + THREADS * j] = 0u;
        } else {
            if (tid < 256) hist[0][tid] = 0u;
        }
        __syncthreads();

        const unsigned prefix = sh_prefix;
        const int k = sh_k;

        if (level == 0) {
            unsigned* h = hist[(tid >> 5) & (NH - 1)];  // warp-group-private copy
            #pragma unroll
            for (int j = 0; j < KPT; j++)
                atomicAdd(&h[key[j] >> 24], 1u);
        } else {
            #pragma unroll
            for (int j = 0; j < KPT; j++) {
                unsigned kk = key[j];
                if ((kk & decided) == prefix)
                    atomicAdd(&hist[0][(kk >> shift) & 0xFFu], 1u);
            }
        }
        __syncthreads();

        // Parallel suffix-sum over 256 bins.
        unsigned v = 0, s = 0;
        if (tid < 256) {
            if (level == 0) {
                #pragma unroll
                for (int c = 0; c < NH; c++) v += hist[c][tid];
            } else {
                v = hist[0][tid];
            }
            s = v;
            int lane = tid & 31;
            #pragma unroll
            for (int off = 1; off < 32; off <<= 1) {
                unsigned t = __shfl_down_sync(0xFFFFFFFFu, s, off);
                if (lane + off < 32) s += t;
            }
            if (lane == 0) warpTot[tid >> 5] = s;
        }
        __syncthreads();
        if (tid < 256) {
            unsigned above = 0;
            #pragma unroll
            for (int w = 0; w < 8; w++)
                if (w > (tid >> 5)) above += warpTot[w];
            unsigned ssum = s + above;                 // count of keys >= start of bin 'tid'
            if (ssum >= (unsigned)k && (ssum - v) < (unsigned)k) {
                sh_prefix = prefix | ((unsigned)tid << shift);
                sh_k = k - (int)(ssum - v);
            }
        }
        decided |= 0xFFu << shift;
        __syncthreads();
    }

    const unsigned T = sh_prefix;   // exact key of the K-th largest element

    // ---- Write binary mask straight from registers ----
    float4* __restrict__ orow = (float4*)(out + rowOff);
    #pragma unroll
    for (int i = 0; i < VPT4; i++) {
        int v = tid + THREADS * i;
        float4 m;
        m.x = (key[4*i + 0] >= T) ? 1.0f : 0.0f;
        m.y = (key[4*i + 1] >= T) ? 1.0f : 0.0f;
        m.z = (key[4*i + 2] >= T) ? 1.0f : 0.0f;
        m.w = (key[4*i + 3] >= T) ? 1.0f : 0.0f;
        __stcs(&orow[v], m);
    }
}

extern "C" void kernel_launch(void* const* d_in, const int* in_sizes, int n_in,
                              void* d_out, int out_size) {
    const float* x    = (const float*)d_in[0];   // (B, N) float32
    const float* duty = (const float*)d_in[1];   // (N,)   float32
    float* out        = (float*)d_out;

    const int n = in_sizes[1];                   // 16384
    const int B = in_sizes[0] / n;               // 4096
    const float targetDensity = (float)K_TOP / (float)n;

    boost_kernel<<<(n + 255) / 256, 256>>>(duty, n, targetDensity);
    kwinners_kernel<<<B, THREADS>>>(x, out);
}